// round 1
// baseline (speedup 1.0000x reference)
#include <cuda_runtime.h>
#include <math.h>

// FlexibleLogisticModel: f = sigmoid( sum_f w[f] * alpha[ord(f)] * monomial_f(x) )
// over all multiset monomials of degree 0..4 in D=64 vars, in
// combinations_with_replacement lex order. We enumerate combos directly and
// NEVER read the 208MB exponent matrix E.
//
// Inputs (metadata order): d_in[0]=x[64] f32, d_in[1]=w[814385] f32,
// d_in[2]=alphas[5] f32, d_in[3]=E (ignored), d_in[4]=ord_ids (ignored).
// Output: 1 float.

#define D 64
#define BASE2 65
#define BASE3 2145
#define BASE4 47905
#define N_TRIPLES 45760   // C(66,3): deg-4 (i1,i2,i3) prefixes
#define N_PAIRS   2080    // C(65,2): deg-3 (i1,i2) prefixes
#define N_UNITS   47905   // 45760 + 2080 + 64 + 1
#define TPB 256
#define NBLK ((N_UNITS + TPB - 1) / TPB)   // 188

__device__ double g_acc = 0.0;

__device__ __forceinline__ int C2i(int n) { return (n >= 2) ? (n * (n - 1)) / 2 : 0; }
__device__ __forceinline__ int C3i(int n) { return (n >= 3) ? (n * (n - 1) * (n - 2)) / 6 : 0; }
__device__ __forceinline__ int C4i(int n) { return (n >= 4) ? (n * (n - 1) * (n - 2) * (n - 3)) / 24 : 0; }

__global__ void __launch_bounds__(TPB)
poly_sum_kernel(const float* __restrict__ x,
                const float* __restrict__ w,
                const float* __restrict__ alphas)
{
    __shared__ float xs[D];
    __shared__ float al[5];
    __shared__ double warp_sums[TPB / 32];

    const int tid = threadIdx.x;
    if (tid < D) xs[tid] = x[tid];
    if (tid < 5) al[tid] = alphas[tid];
    __syncthreads();

    const int u = blockIdx.x * TPB + tid;
    double local = 0.0;

    if (u < N_TRIPLES) {
        // ---- degree-4: this thread owns triple-rank t = u; loop over i4 ----
        const int t = u;
        // i1: largest a with P(a) = C3(66) - C3(66-a) <= t
        int i1 = 0;
        while (i1 < 63 && (N_TRIPLES - C3i(66 - (i1 + 1))) <= t) i1++;
        const int r1 = t - (N_TRIPLES - C3i(66 - i1));
        // i2: largest b >= i1 with Q(b) = C2(65-i1) - C2(65-b) <= r1
        const int qi1 = C2i(65 - i1);
        int i2 = i1;
        while (i2 < 63 && (qi1 - C2i(65 - (i2 + 1))) <= r1) i2++;
        const int r2 = r1 - (qi1 - C2i(65 - i2));
        const int i3 = i2 + r2;

        const int off = BASE4
                      + (766480 - C4i(67 - i1))
                      + (C3i(66 - i1) - C3i(66 - i2))
                      + (C2i(65 - i2) - C2i(65 - i3));
        const float p = xs[i1] * xs[i2] * xs[i3] * al[4];
        float s = 0.0f;
        #pragma unroll 4
        for (int i4 = i3; i4 < D; i4++)
            s += w[off + (i4 - i3)] * xs[i4];
        local = (double)(p * s);
    } else if (u < N_TRIPLES + N_PAIRS) {
        // ---- degree-3: this thread owns pair-rank p; loop over i3 ----
        const int pr = u - N_TRIPLES;
        // i1: largest a with V(a) = C2(65) - C2(65-a) <= pr
        int i1 = 0;
        while (i1 < 63 && (N_PAIRS - C2i(65 - (i1 + 1))) <= pr) i1++;
        const int i2 = i1 + (pr - (N_PAIRS - C2i(65 - i1)));

        const int off = BASE3
                      + (N_TRIPLES - C3i(66 - i1))
                      + (C2i(65 - i1) - C2i(65 - i2));
        const float p = xs[i1] * xs[i2] * al[3];
        float s = 0.0f;
        #pragma unroll 4
        for (int i3 = i2; i3 < D; i3++)
            s += w[off + (i3 - i2)] * xs[i3];
        local = (double)(p * s);
    } else if (u < N_TRIPLES + N_PAIRS + D) {
        // ---- degree-2: this thread owns leading index i1; loop over i2 ----
        const int i1 = u - (N_TRIPLES + N_PAIRS);
        const int off = BASE2 + (N_PAIRS - C2i(65 - i1));
        const float p = xs[i1] * al[2];
        float s = 0.0f;
        #pragma unroll 4
        for (int i2 = i1; i2 < D; i2++)
            s += w[off + (i2 - i1)] * xs[i2];
        local = (double)(p * s);
    } else if (u == N_TRIPLES + N_PAIRS + D) {
        // ---- degree 0 and 1 ----
        double s = (double)(w[0] * al[0]);
        float s1 = 0.0f;
        #pragma unroll 4
        for (int i = 0; i < D; i++)
            s1 += w[1 + i] * xs[i];
        local = s + (double)(al[1] * s1);
    }

    // ---- block reduction (double) ----
    #pragma unroll
    for (int o = 16; o > 0; o >>= 1)
        local += __shfl_down_sync(0xffffffffu, local, o);
    if ((tid & 31) == 0) warp_sums[tid >> 5] = local;
    __syncthreads();
    if (tid == 0) {
        double bs = 0.0;
        #pragma unroll
        for (int i = 0; i < TPB / 32; i++) bs += warp_sums[i];
        atomicAdd(&g_acc, bs);
    }
}

__global__ void finalize_kernel(float* __restrict__ out)
{
    const double a = g_acc;
    out[0] = (float)(1.0 / (1.0 + exp(-a)));
    g_acc = 0.0;  // reset for next graph replay (deterministic)
}

extern "C" void kernel_launch(void* const* d_in, const int* in_sizes, int n_in,
                              void* d_out, int out_size)
{
    const float* x      = (const float*)d_in[0];
    const float* w      = (const float*)d_in[1];
    const float* alphas = (const float*)d_in[2];
    // d_in[3] = E (constant exponents, NOT read), d_in[4] = ord_ids (NOT read)
    float* out = (float*)d_out;

    poly_sum_kernel<<<NBLK, TPB>>>(x, w, alphas);
    finalize_kernel<<<1, 1>>>(out);
}